// round 6
// baseline (speedup 1.0000x reference)
#include <cuda_runtime.h>
#include <cuda_bf16.h>

// Cosine similarity + segmented mean.
// x1, x2: [N, 65536] fp32. out: [N/n] fp32.
//
// Stage1 frozen at the empirically fastest geometry (512 CTAs x 512 thr,
// unroll-4). Only change this round: loads use
// ld.global.nc.L1::no_allocate.L2::256B (skip L1 allocation + 256B L2
// fetch granularity) to probe the last untried load-path lever against
// the 6.0 TB/s plateau. Stage2 finalize rides PDL (neutral-positive in R5).

#define VEC_D       65536
#define VEC_D4      (VEC_D / 4)     // 16384 float4 per sample
#define T1          512
#define MAX_SAMPLES 1024

__device__ float g_dot[MAX_SAMPLES];
__device__ float g_n1[MAX_SAMPLES];
__device__ float g_n2[MAX_SAMPLES];

__device__ __forceinline__ float warp_sum(float v) {
    #pragma unroll
    for (int off = 16; off > 0; off >>= 1)
        v += __shfl_xor_sync(0xFFFFFFFFu, v, off);
    return v;
}

// Streaming 128-bit load: non-coherent, no L1 allocation, 256B L2 fetch.
__device__ __forceinline__ float4 ld_stream4(const float4* p) {
    float4 v;
    asm volatile(
        "ld.global.nc.L1::no_allocate.L2::256B.v4.f32 {%0, %1, %2, %3}, [%4];"
        : "=f"(v.x), "=f"(v.y), "=f"(v.z), "=f"(v.w)
        : "l"(p));
    return v;
}

__global__ void __launch_bounds__(T1)
cos_stage1(const float* __restrict__ x1, const float* __restrict__ x2) {
    const int s = blockIdx.x;
    const float4* __restrict__ a =
        reinterpret_cast<const float4*>(x1) + (size_t)s * VEC_D4;
    const float4* __restrict__ b =
        reinterpret_cast<const float4*>(x2) + (size_t)s * VEC_D4;

    float dot = 0.0f, n1 = 0.0f, n2 = 0.0f;

    #pragma unroll 4
    for (int i = threadIdx.x; i < VEC_D4; i += T1) {
        float4 av = ld_stream4(a + i);
        float4 bv = ld_stream4(b + i);
        dot = fmaf(av.x, bv.x, dot);
        dot = fmaf(av.y, bv.y, dot);
        dot = fmaf(av.z, bv.z, dot);
        dot = fmaf(av.w, bv.w, dot);
        n1  = fmaf(av.x, av.x, n1);
        n1  = fmaf(av.y, av.y, n1);
        n1  = fmaf(av.z, av.z, n1);
        n1  = fmaf(av.w, av.w, n1);
        n2  = fmaf(bv.x, bv.x, n2);
        n2  = fmaf(bv.y, bv.y, n2);
        n2  = fmaf(bv.z, bv.z, n2);
        n2  = fmaf(bv.w, bv.w, n2);
    }

    __shared__ float s_dot[T1 / 32];
    __shared__ float s_n1[T1 / 32];
    __shared__ float s_n2[T1 / 32];

    dot = warp_sum(dot);
    n1  = warp_sum(n1);
    n2  = warp_sum(n2);

    const int lane = threadIdx.x & 31;
    const int wid  = threadIdx.x >> 5;
    if (lane == 0) {
        s_dot[wid] = dot;
        s_n1[wid]  = n1;
        s_n2[wid]  = n2;
    }
    __syncthreads();

    if (wid == 0) {
        dot = (lane < T1 / 32) ? s_dot[lane] : 0.0f;
        n1  = (lane < T1 / 32) ? s_n1[lane]  : 0.0f;
        n2  = (lane < T1 / 32) ? s_n2[lane]  : 0.0f;
        dot = warp_sum(dot);
        n1  = warp_sum(n1);
        n2  = warp_sum(n2);
        if (lane == 0) {
            g_dot[s] = dot;
            g_n1[s]  = n1;
            g_n2[s]  = n2;
        }
    }
    __syncthreads();
    cudaTriggerProgrammaticLaunchCompletion();
}

__global__ void cos_stage2(float* __restrict__ out, int n_per_group,
                           int n_groups) {
    cudaGridDependencySynchronize();
    const int g = blockIdx.x * blockDim.x + threadIdx.x;
    if (g >= n_groups) return;
    float acc = 0.0f;
    for (int j = 0; j < n_per_group; j++) {
        const int s = g * n_per_group + j;
        const float denom = sqrtf(g_n1[s]) * sqrtf(g_n2[s]);
        acc += g_dot[s] / fmaxf(denom, 1e-8f);
    }
    out[g] = acc / (float)n_per_group;
}

extern "C" void kernel_launch(void* const* d_in, const int* in_sizes, int n_in,
                              void* d_out, int out_size) {
    const float* x1 = (const float*)d_in[0];
    const float* x2 = (const float*)d_in[1];
    const int N = in_sizes[0] / VEC_D;        // 512
    const int n_groups = out_size;            // 64
    const int n_per_group = N / n_groups;     // 8
    float* out = (float*)d_out;

    cos_stage1<<<N, T1>>>(x1, x2);

    cudaLaunchAttribute attr;
    attr.id = cudaLaunchAttributeProgrammaticStreamSerialization;
    attr.val.programmaticStreamSerializationAllowed = 1;
    cudaLaunchConfig_t cfg = {};
    cfg.gridDim  = dim3(1, 1, 1);
    cfg.blockDim = dim3(64, 1, 1);
    cfg.dynamicSmemBytes = 0;
    cfg.stream = 0;
    cfg.attrs = &attr;
    cfg.numAttrs = 1;
    cudaLaunchKernelEx(&cfg, cos_stage2, out, n_per_group, n_groups);
}

// round 7
// speedup vs baseline: 1.2100x; 1.2100x over previous
#include <cuda_runtime.h>
#include <cuda_bf16.h>

// Cosine similarity + segmented mean.
// x1, x2: [N, 65536] fp32. out: [N/n] fp32.
//
// R7 probe: 256-bit global loads (LDG.E.256 via CUDA-13 double4_32a,
// 32-byte aligned) — halves LDG/L1tex-wavefront count per byte vs float4.
// Floats are bit-extracted from the double carriers (exact).
// Structure otherwise frozen at best-known R5 (512x512 stage1, PDL stage2).

#define VEC_D       65536
#define VEC_D8      (VEC_D / 8)     // 8192 x 32-byte chunks per sample
#define T1          512
#define MAX_SAMPLES 1024

__device__ float g_dot[MAX_SAMPLES];
__device__ float g_n1[MAX_SAMPLES];
__device__ float g_n2[MAX_SAMPLES];

__device__ __forceinline__ float warp_sum(float v) {
    #pragma unroll
    for (int off = 16; off > 0; off >>= 1)
        v += __shfl_xor_sync(0xFFFFFFFFu, v, off);
    return v;
}

// Process one pair of 64-bit carriers = 2 float lanes from each stream.
__device__ __forceinline__ void proc2(double ad, double bd,
                                      float& dot, float& n1, float& n2) {
    const float a0 = __int_as_float(__double2loint(ad));
    const float a1 = __int_as_float(__double2hiint(ad));
    const float b0 = __int_as_float(__double2loint(bd));
    const float b1 = __int_as_float(__double2hiint(bd));
    dot = fmaf(a0, b0, dot); dot = fmaf(a1, b1, dot);
    n1  = fmaf(a0, a0, n1);  n1  = fmaf(a1, a1, n1);
    n2  = fmaf(b0, b0, n2);  n2  = fmaf(b1, b1, n2);
}

__global__ void __launch_bounds__(T1)
cos_stage1(const float* __restrict__ x1, const float* __restrict__ x2) {
    const int s = blockIdx.x;
    const double4_32a* __restrict__ a =
        reinterpret_cast<const double4_32a*>(x1) + (size_t)s * VEC_D8;
    const double4_32a* __restrict__ b =
        reinterpret_cast<const double4_32a*>(x2) + (size_t)s * VEC_D8;

    float dot = 0.0f, n1 = 0.0f, n2 = 0.0f;

    // 8192 chunks / 512 threads = 16 iterations.
    #pragma unroll 4
    for (int i = threadIdx.x; i < VEC_D8; i += T1) {
        double4_32a av = a[i];
        double4_32a bv = b[i];
        proc2(av.x, bv.x, dot, n1, n2);
        proc2(av.y, bv.y, dot, n1, n2);
        proc2(av.z, bv.z, dot, n1, n2);
        proc2(av.w, bv.w, dot, n1, n2);
    }

    __shared__ float s_dot[T1 / 32];
    __shared__ float s_n1[T1 / 32];
    __shared__ float s_n2[T1 / 32];

    dot = warp_sum(dot);
    n1  = warp_sum(n1);
    n2  = warp_sum(n2);

    const int lane = threadIdx.x & 31;
    const int wid  = threadIdx.x >> 5;
    if (lane == 0) {
        s_dot[wid] = dot;
        s_n1[wid]  = n1;
        s_n2[wid]  = n2;
    }
    __syncthreads();

    if (wid == 0) {
        dot = (lane < T1 / 32) ? s_dot[lane] : 0.0f;
        n1  = (lane < T1 / 32) ? s_n1[lane]  : 0.0f;
        n2  = (lane < T1 / 32) ? s_n2[lane]  : 0.0f;
        dot = warp_sum(dot);
        n1  = warp_sum(n1);
        n2  = warp_sum(n2);
        if (lane == 0) {
            g_dot[s] = dot;
            g_n1[s]  = n1;
            g_n2[s]  = n2;
        }
    }
    __syncthreads();
    // Writes above are visible to the PDL secondary after its
    // cudaGridDependencySynchronize (trigger placed after the writes).
    cudaTriggerProgrammaticLaunchCompletion();
}

__global__ void cos_stage2(float* __restrict__ out, int n_per_group,
                           int n_groups) {
    cudaGridDependencySynchronize();
    const int g = blockIdx.x * blockDim.x + threadIdx.x;
    if (g >= n_groups) return;
    float acc = 0.0f;
    for (int j = 0; j < n_per_group; j++) {
        const int s = g * n_per_group + j;
        const float denom = sqrtf(g_n1[s]) * sqrtf(g_n2[s]);
        acc += g_dot[s] / fmaxf(denom, 1e-8f);
    }
    out[g] = acc / (float)n_per_group;
}

extern "C" void kernel_launch(void* const* d_in, const int* in_sizes, int n_in,
                              void* d_out, int out_size) {
    const float* x1 = (const float*)d_in[0];
    const float* x2 = (const float*)d_in[1];
    const int N = in_sizes[0] / VEC_D;        // 512
    const int n_groups = out_size;            // 64
    const int n_per_group = N / n_groups;     // 8
    float* out = (float*)d_out;

    cos_stage1<<<N, T1>>>(x1, x2);

    cudaLaunchAttribute attr;
    attr.id = cudaLaunchAttributeProgrammaticStreamSerialization;
    attr.val.programmaticStreamSerializationAllowed = 1;
    cudaLaunchConfig_t cfg = {};
    cfg.gridDim  = dim3(1, 1, 1);
    cfg.blockDim = dim3(64, 1, 1);
    cfg.dynamicSmemBytes = 0;
    cfg.stream = 0;
    cfg.attrs = &attr;
    cfg.numAttrs = 1;
    cudaLaunchKernelEx(&cfg, cos_stage2, out, n_per_group, n_groups);
}